// round 15
// baseline (speedup 1.0000x reference)
#include <cuda_runtime.h>
#include <cuda_fp16.h>
#include <mma.h>
#include <cstdint>

#define CDIM    128
#define NNODES  100000
#define NEDGES  200000
#define ADJ_MAX 3200000
#define INC_MAX 400000
#define NTOT    (NNODES + NEDGES + NNODES)
#define NINC    (NEDGES + NNODES)                 // 300000 inc-side rows
#define E_MAX   (ADJ_MAX + 2 * INC_MAX)
#define LDH     136

using namespace nvcuda;

// ---------------- scratch ----------------
__device__ __align__(128) __half g_hx [(size_t)NNODES * CDIM];   // x fp16
__device__ __align__(128) __half g_h1 [(size_t)NNODES * CDIM];   // x@W1_00
__device__ __align__(128) __half g_h2 [(size_t)NNODES * CDIM];   // x@W1_01
__device__ __align__(128) __half g_hB [(size_t)NNODES * CDIM];   // nodes_l1 = sig(adj@h1)
__device__ __align__(128) __half g_hC [(size_t)NEDGES * CDIM];   // edges_l1 = sig(incT@h2)
__device__ __align__(128) __half g_q  [(size_t)NNODES * CDIM];   // adj @ nodes_l1
__device__ __align__(128) __half g_r  [(size_t)NNODES * CDIM];   // inc @ edges_l1
__device__ __align__(128) __half g_pf [(size_t)NNODES * CDIM];   // (inc@edges_l1)@W2_10
__device__ __align__(128) __half g_hW [4][CDIM * CDIM];

__device__ int  g_cnt [NTOT];          // adj: [0,100k)  inc: [100k,400k)
__device__ int  g_work[NTOT];
__device__ int  g_ptr [NNODES + 1];    // adj CSR
__device__ int  g_ptr2[NINC + 1];      // incT rows then inc rows
__device__ int2 g_e   [E_MAX];
__device__ int  g_sums[256];           // [0:128) adj, [128:256) inc

__device__ __forceinline__ float sigf(float x) { return 1.f / (1.f + __expf(-x)); }
__device__ __forceinline__ unsigned h2u(__half2 h) { return *reinterpret_cast<unsigned*>(&h); }

// ---------------- converts: x + all 4 weights in ONE kernel ----------------
__global__ __launch_bounds__(256) void f2h_all(const float4* __restrict__ x, int xN4,
                                               const float4* __restrict__ w0,
                                               const float4* __restrict__ w1,
                                               const float4* __restrict__ w2,
                                               const float4* __restrict__ w3,
                                               uint2* __restrict__ outx,
                                               uint2* __restrict__ outw)
{
    int i = blockIdx.x * blockDim.x + threadIdx.x;
    if (i < xN4) {
        float4 v = x[i];
        outx[i] = make_uint2(h2u(__floats2half2_rn(v.x, v.y)),
                             h2u(__floats2half2_rn(v.z, v.w)));
    } else {
        int j = i - xN4;
        if (j < 16384) {
            const float4* src = (j < 4096) ? w0 : (j < 8192) ? w1 : (j < 12288) ? w2 : w3;
            float4 v = src[j & 4095];
            outw[j] = make_uint2(h2u(__floats2half2_rn(v.x, v.y)),
                                 h2u(__floats2half2_rn(v.z, v.w)));
        }
    }
}

// ---------------- tensor-core GEMM: outH = half(A @ W) ----------------
__global__ __launch_bounds__(256, 2) void gemm_tc(const __half* __restrict__ A,
                                                  const __half* __restrict__ W,
                                                  __half* __restrict__ out, int M)
{
    extern __shared__ char smem[];
    __half* sA = reinterpret_cast<__half*>(smem);
    __half* sW = reinterpret_cast<__half*>(smem + 128 * LDH * 2);
    float*  sO = reinterpret_cast<float*>(smem);

    const int tid  = threadIdx.x;
    const int row0 = blockIdx.x * 128;

    #pragma unroll
    for (int i = 0; i < 8; ++i) {
        int e = tid + i * 256;
        int r = e >> 4, c = e & 15;
        uint4 v = reinterpret_cast<const uint4*>(W)[e];
        *reinterpret_cast<uint4*>(&sW[r * LDH + c * 8]) = v;
    }
    #pragma unroll
    for (int i = 0; i < 8; ++i) {
        int e = tid + i * 256;
        int r = e >> 4, c = e & 15;
        uint4 v = make_uint4(0u, 0u, 0u, 0u);
        if (row0 + r < M) v = reinterpret_cast<const uint4*>(A)[(size_t)(row0 + r) * 16 + c];
        *reinterpret_cast<uint4*>(&sA[r * LDH + c * 8]) = v;
    }
    __syncthreads();

    const int warpId = tid >> 5;
    const int wr = warpId >> 1;
    const int wc = warpId & 1;

    wmma::fragment<wmma::accumulator, 16, 16, 16, float> c[2][4];
    #pragma unroll
    for (int i = 0; i < 2; ++i)
        #pragma unroll
        for (int j = 0; j < 4; ++j) wmma::fill_fragment(c[i][j], 0.f);

    #pragma unroll
    for (int k = 0; k < 8; ++k) {
        wmma::fragment<wmma::matrix_a, 16, 16, 16, __half, wmma::row_major> a[2];
        wmma::fragment<wmma::matrix_b, 16, 16, 16, __half, wmma::row_major> b[4];
        #pragma unroll
        for (int i = 0; i < 2; ++i)
            wmma::load_matrix_sync(a[i], &sA[(wr * 32 + i * 16) * LDH + k * 16], LDH);
        #pragma unroll
        for (int j = 0; j < 4; ++j)
            wmma::load_matrix_sync(b[j], &sW[(k * 16) * LDH + wc * 64 + j * 16], LDH);
        #pragma unroll
        for (int i = 0; i < 2; ++i)
            #pragma unroll
            for (int j = 0; j < 4; ++j)
                wmma::mma_sync(c[i][j], a[i], b[j], c[i][j]);
    }

    __syncthreads();
    #pragma unroll
    for (int i = 0; i < 2; ++i)
        #pragma unroll
        for (int j = 0; j < 4; ++j)
            wmma::store_matrix_sync(&sO[(wr * 32 + i * 16) * 128 + wc * 64 + j * 16],
                                    c[i][j], 128, wmma::mem_row_major);
    __syncthreads();

    #pragma unroll
    for (int i = 0; i < 16; ++i) {
        int e  = tid + i * 256;
        int r  = e >> 5, c4 = e & 31;
        int grow = row0 + r;
        if (grow < M) {
            float4 v = reinterpret_cast<float4*>(sO)[(size_t)r * 32 + c4];
            uint2 o = make_uint2(h2u(__floats2half2_rn(v.x, v.y)),
                                 h2u(__floats2half2_rn(v.z, v.w)));
            reinterpret_cast<uint2*>(out)[(size_t)grow * 32 + c4] = o;
        }
    }
}

// ---------------- fused final GEMM: out = sigmoid(A @ W + pf), fp32 out ----------
__global__ __launch_bounds__(256, 2) void gemm_final(const __half* __restrict__ A,
                                                     const __half* __restrict__ W,
                                                     const __half* __restrict__ pf,
                                                     float* __restrict__ out, int M)
{
    extern __shared__ char smem[];
    __half* sA = reinterpret_cast<__half*>(smem);
    __half* sW = reinterpret_cast<__half*>(smem + 128 * LDH * 2);
    float*  sO = reinterpret_cast<float*>(smem);

    const int tid  = threadIdx.x;
    const int row0 = blockIdx.x * 128;

    #pragma unroll
    for (int i = 0; i < 8; ++i) {
        int e = tid + i * 256;
        int r = e >> 4, c = e & 15;
        uint4 v = reinterpret_cast<const uint4*>(W)[e];
        *reinterpret_cast<uint4*>(&sW[r * LDH + c * 8]) = v;
    }
    #pragma unroll
    for (int i = 0; i < 8; ++i) {
        int e = tid + i * 256;
        int r = e >> 4, c = e & 15;
        uint4 v = make_uint4(0u, 0u, 0u, 0u);
        if (row0 + r < M) v = reinterpret_cast<const uint4*>(A)[(size_t)(row0 + r) * 16 + c];
        *reinterpret_cast<uint4*>(&sA[r * LDH + c * 8]) = v;
    }
    __syncthreads();

    const int warpId = tid >> 5;
    const int wr = warpId >> 1;
    const int wc = warpId & 1;

    wmma::fragment<wmma::accumulator, 16, 16, 16, float> c[2][4];
    #pragma unroll
    for (int i = 0; i < 2; ++i)
        #pragma unroll
        for (int j = 0; j < 4; ++j) wmma::fill_fragment(c[i][j], 0.f);

    #pragma unroll
    for (int k = 0; k < 8; ++k) {
        wmma::fragment<wmma::matrix_a, 16, 16, 16, __half, wmma::row_major> a[2];
        wmma::fragment<wmma::matrix_b, 16, 16, 16, __half, wmma::row_major> b[4];
        #pragma unroll
        for (int i = 0; i < 2; ++i)
            wmma::load_matrix_sync(a[i], &sA[(wr * 32 + i * 16) * LDH + k * 16], LDH);
        #pragma unroll
        for (int j = 0; j < 4; ++j)
            wmma::load_matrix_sync(b[j], &sW[(k * 16) * LDH + wc * 64 + j * 16], LDH);
        #pragma unroll
        for (int i = 0; i < 2; ++i)
            #pragma unroll
            for (int j = 0; j < 4; ++j)
                wmma::mma_sync(c[i][j], a[i], b[j], c[i][j]);
    }

    __syncthreads();
    #pragma unroll
    for (int i = 0; i < 2; ++i)
        #pragma unroll
        for (int j = 0; j < 4; ++j)
            wmma::store_matrix_sync(&sO[(wr * 32 + i * 16) * 128 + wc * 64 + j * 16],
                                    c[i][j], 128, wmma::mem_row_major);
    __syncthreads();

    #pragma unroll
    for (int i = 0; i < 16; ++i) {
        int e  = tid + i * 256;
        int r  = e >> 5, c4 = e & 31;
        int grow = row0 + r;
        if (grow < M) {
            float4 v = reinterpret_cast<float4*>(sO)[(size_t)r * 32 + c4];
            uint2 pu = reinterpret_cast<const uint2*>(pf)[(size_t)grow * 32 + c4];
            float2 p0 = __half22float2(*reinterpret_cast<__half2*>(&pu.x));
            float2 p1 = __half22float2(*reinterpret_cast<__half2*>(&pu.y));
            float4 o = make_float4(sigf(v.x + p0.x), sigf(v.y + p0.y),
                                   sigf(v.z + p1.x), sigf(v.w + p1.y));
            reinterpret_cast<float4*>(out)[(size_t)grow * 32 + c4] = o;
        }
    }
}

// ---------------- CSR builds ----------------
__global__ __launch_bounds__(256) void hist_adj(const int* __restrict__ rows, int nnz,
                                                int* __restrict__ cnt)
{
    int i = blockIdx.x * blockDim.x + threadIdx.x;
    if (i < nnz) atomicAdd(&cnt[rows[i]], 1);
}

__global__ __launch_bounds__(256) void hist_inc(const int* __restrict__ inc_rows,
                                                const int* __restrict__ inc_cols, int nnz,
                                                int* __restrict__ cnt)
{
    int i = blockIdx.x * blockDim.x + threadIdx.x;
    if (i < nnz) {
        atomicAdd(&cnt[inc_cols[i]], 1);            // incT rows (edge ids)
        atomicAdd(&cnt[NEDGES + inc_rows[i]], 1);   // inc rows (node ids)
    }
}

__global__ __launch_bounds__(1024) void scan_chunk(const int* __restrict__ in,
                                                   int* __restrict__ out,
                                                   int* __restrict__ sums, int n)
{
    __shared__ int sh[1024];
    int t = threadIdx.x;
    int idx = blockIdx.x * 4096 + t * 4;
    int a0 = (idx     < n) ? in[idx]     : 0;
    int a1 = (idx + 1 < n) ? in[idx + 1] : 0;
    int a2 = (idx + 2 < n) ? in[idx + 2] : 0;
    int a3 = (idx + 3 < n) ? in[idx + 3] : 0;
    int s = a0 + a1 + a2 + a3;
    sh[t] = s;
    __syncthreads();
    for (int off = 1; off < 1024; off <<= 1) {
        int v = (t >= off) ? sh[t - off] : 0;
        __syncthreads();
        sh[t] += v;
        __syncthreads();
    }
    int excl = sh[t] - s;
    if (idx     < n) out[idx]     = excl;
    if (idx + 1 < n) out[idx + 1] = excl + a0;
    if (idx + 2 < n) out[idx + 2] = excl + a0 + a1;
    if (idx + 3 < n) out[idx + 3] = excl + a0 + a1 + a2;
    if (t == 1023) sums[blockIdx.x] = sh[1023];
}

__global__ __launch_bounds__(256) void add_base_scan(int* __restrict__ ptr,
                                                     int* __restrict__ work,
                                                     const int* __restrict__ sums,
                                                     int n, int base, int end)
{
    __shared__ int sh[128];
    int t = threadIdx.x;
    if (t < 128) sh[t] = sums[t];
    __syncthreads();
    for (int off = 1; off < 128; off <<= 1) {
        int v = (t < 128 && t >= off) ? sh[t - off] : 0;
        __syncthreads();
        if (t < 128) sh[t] += v;
        __syncthreads();
    }
    int i = blockIdx.x * blockDim.x + t;
    if (i < n) {
        int blk = i >> 12;
        int pre = (blk == 0) ? 0 : sh[blk - 1];
        int v = ptr[i] + pre + base;
        ptr[i]  = v;
        work[i] = v;
    }
    if (i == 0) ptr[n] = end;
}

__global__ __launch_bounds__(256) void scatter_adj(const int* __restrict__ rows,
                                                   const int* __restrict__ cols,
                                                   const float* __restrict__ vals, int nnz,
                                                   int* __restrict__ work,
                                                   int2* __restrict__ e)
{
    int i = blockIdx.x * blockDim.x + threadIdx.x;
    if (i >= nnz) return;
    int p = atomicAdd(&work[rows[i]], 1);
    e[p] = make_int2(cols[i], __float_as_int(vals[i]));
}

__global__ __launch_bounds__(256) void scatter_inc(const int* __restrict__ inc_rows,
                                                   const int* __restrict__ inc_cols,
                                                   const float* __restrict__ inc_vals, int nnz,
                                                   int* __restrict__ work,
                                                   int2* __restrict__ e)
{
    int i = blockIdx.x * blockDim.x + threadIdx.x;
    if (i >= nnz) return;
    int vv = __float_as_int(inc_vals[i]);
    int p = atomicAdd(&work[inc_cols[i]], 1);
    e[p] = make_int2(inc_rows[i], vv);
    int q = atomicAdd(&work[NEDGES + inc_rows[i]], 1);
    e[q] = make_int2(inc_cols[i], vv);
}

// ---------------- CSR SpMM: warp per row, fp16 in, fp16 out (optional sigmoid) -----
__device__ __forceinline__ void gather_fma(float4& acc, int2 t,
                                           const uint2* __restrict__ Xu, int lane)
{
    float v  = __int_as_float(t.y);
    uint2 u  = __ldg(&Xu[(size_t)t.x * 32 + lane]);
    float2 f0 = __half22float2(*reinterpret_cast<__half2*>(&u.x));
    float2 f1 = __half22float2(*reinterpret_cast<__half2*>(&u.y));
    acc.x += v * f0.x; acc.y += v * f0.y; acc.z += v * f1.x; acc.w += v * f1.y;
}

__global__ __launch_bounds__(256) void spmm_h(const int* __restrict__ ptr,
                                              const int2* __restrict__ e,
                                              const __half* __restrict__ X,
                                              __half* __restrict__ out,
                                              int nrows, int applySig)
{
    __shared__ int2 se[8][32];
    int w    = (blockIdx.x * blockDim.x + threadIdx.x) >> 5;
    int lane = threadIdx.x & 31;
    int wl   = threadIdx.x >> 5;
    if (w >= nrows) return;
    const uint2* Xu = reinterpret_cast<const uint2*>(X);
    int start = ptr[w], end = ptr[w + 1];
    float4 acc = make_float4(0.f, 0.f, 0.f, 0.f);
    for (int i = start; i < end; i += 32) {
        int take = min(32, end - i);
        if (lane < take) se[wl][lane] = e[i + lane];
        __syncwarp();
        if (take == 32) {
            #pragma unroll 8
            for (int j = 0; j < 32; ++j) gather_fma(acc, se[wl][j], Xu, lane);
        } else {
            for (int j = 0; j < take; ++j) gather_fma(acc, se[wl][j], Xu, lane);
        }
        __syncwarp();
    }
    if (applySig) {
        acc.x = sigf(acc.x); acc.y = sigf(acc.y); acc.z = sigf(acc.z); acc.w = sigf(acc.w);
    }
    uint2 o = make_uint2(h2u(__floats2half2_rn(acc.x, acc.y)),
                         h2u(__floats2half2_rn(acc.z, acc.w)));
    reinterpret_cast<uint2*>(out)[(size_t)w * 32 + lane] = o;
}

// ---------------- host ----------------
extern "C" void kernel_launch(void* const* d_in, const int* in_sizes, int n_in,
                              void* d_out, int out_size)
{
    const float* x        = (const float*)d_in[0];
    const float* W1_00    = (const float*)d_in[1];
    const float* W1_01    = (const float*)d_in[2];
    const float* W2_00    = (const float*)d_in[3];
    const float* W2_10    = (const float*)d_in[4];
    const int*   adj_rows = (const int*)  d_in[5];
    const int*   adj_cols = (const int*)  d_in[6];
    const float* adj_vals = (const float*)d_in[7];
    const int*   inc_rows = (const int*)  d_in[8];
    const int*   inc_cols = (const int*)  d_in[9];
    const float* inc_vals = (const float*)d_in[10];
    const int adj_nnz = in_sizes[5];
    const int inc_nnz = in_sizes[8];
    const int nodes   = NNODES;
    const int edges   = NEDGES;

    __half *hx, *h1, *h2, *hB, *hC, *q, *r, *pf, *hW;
    int *cnt, *ptr, *ptr2, *work, *sums;
    int2 *eAll;
    cudaGetSymbolAddress((void**)&hx, g_hx);
    cudaGetSymbolAddress((void**)&h1, g_h1);
    cudaGetSymbolAddress((void**)&h2, g_h2);
    cudaGetSymbolAddress((void**)&hB, g_hB);
    cudaGetSymbolAddress((void**)&hC, g_hC);
    cudaGetSymbolAddress((void**)&q,  g_q);
    cudaGetSymbolAddress((void**)&r,  g_r);
    cudaGetSymbolAddress((void**)&pf, g_pf);
    cudaGetSymbolAddress((void**)&hW, g_hW);
    cudaGetSymbolAddress((void**)&cnt,  g_cnt);
    cudaGetSymbolAddress((void**)&ptr,  g_ptr);
    cudaGetSymbolAddress((void**)&ptr2, g_ptr2);
    cudaGetSymbolAddress((void**)&work, g_work);
    cudaGetSymbolAddress((void**)&sums, g_sums);
    cudaGetSymbolAddress((void**)&eAll, g_e);

    __half* hW0 = hW;
    __half* hW1 = hW + CDIM * CDIM;
    __half* hW2 = hW + 2 * CDIM * CDIM;
    __half* hW3 = hW + 3 * CDIM * CDIM;

    static cudaStream_t s1 = nullptr;
    static cudaEvent_t evFork = nullptr, evG1 = nullptr, evPart = nullptr;
    if (!s1) {
        cudaStreamCreateWithFlags(&s1, cudaStreamNonBlocking);
        cudaEventCreateWithFlags(&evFork, cudaEventDisableTiming);
        cudaEventCreateWithFlags(&evG1,   cudaEventDisableTiming);
        cudaEventCreateWithFlags(&evPart, cudaEventDisableTiming);
        cudaFuncSetAttribute(gemm_tc, cudaFuncAttributeMaxDynamicSharedMemorySize,
                             128 * LDH * 2 * 2);
        cudaFuncSetAttribute(gemm_final, cudaFuncAttributeMaxDynamicSharedMemorySize,
                             128 * LDH * 2 * 2);
    }
    const int SMEM = 128 * LDH * 2 * 2;

    // ---- fork ----
    cudaEventRecord(evFork, 0);
    cudaStreamWaitEvent(s1, evFork, 0);

    // ---- stream 0: adj CSR build ----
    cudaMemsetAsync(cnt, 0, (size_t)NNODES * sizeof(int), 0);
    hist_adj<<<(adj_nnz + 255) / 256, 256>>>(adj_rows, adj_nnz, cnt);
    {
        int nB = (NNODES + 4095) / 4096;
        scan_chunk<<<nB, 1024>>>(cnt, ptr, sums, NNODES);
        add_base_scan<<<(NNODES + 255) / 256, 256>>>(ptr, work, sums, NNODES, 0, adj_nnz);
    }
    scatter_adj<<<(adj_nnz + 255) / 256, 256>>>(adj_rows, adj_cols, adj_vals, adj_nnz,
                                                work, eAll);

    // ---- stream s1: converts + level-1 GEMMs ----
    int xN4 = nodes * CDIM / 4;
    f2h_all<<<(xN4 + 16384 + 255) / 256, 256, 0, s1>>>((const float4*)x, xN4,
                                                       (const float4*)W1_00, (const float4*)W1_01,
                                                       (const float4*)W2_00, (const float4*)W2_10,
                                                       (uint2*)hx, (uint2*)hW0);
    gemm_tc<<<(nodes + 127) / 128, 256, SMEM, s1>>>(hx, hW0, h1, nodes);
    cudaEventRecord(evG1, s1);
    gemm_tc<<<(nodes + 127) / 128, 256, SMEM, s1>>>(hx, hW1, h2, nodes);

    // ---- stream s1: inc CSR build ----
    cudaMemsetAsync(cnt + NNODES, 0, (size_t)NINC * sizeof(int), s1);
    hist_inc<<<(inc_nnz + 255) / 256, 256, 0, s1>>>(inc_rows, inc_cols, inc_nnz, cnt + NNODES);
    {
        int nB = (NINC + 4095) / 4096;
        scan_chunk<<<nB, 1024, 0, s1>>>(cnt + NNODES, ptr2, sums + 128, NINC);
        add_base_scan<<<(NINC + 255) / 256, 256, 0, s1>>>(ptr2, work + NNODES, sums + 128,
                                                          NINC, adj_nnz,
                                                          adj_nnz + 2 * inc_nnz);
    }
    scatter_inc<<<(inc_nnz + 255) / 256, 256, 0, s1>>>(inc_rows, inc_cols, inc_vals, inc_nnz,
                                                       work + NNODES, eAll);

    // ---- stream 0: node chain (S1 -> q) ----
    cudaStreamWaitEvent(0, evG1, 0);
    spmm_h<<<(nodes + 7) / 8, 256>>>(ptr, eAll, h1, hB, nodes, 1);      // nodes_l1
    spmm_h<<<(nodes + 7) / 8, 256>>>(ptr, eAll, hB, q, nodes, 0);       // adj @ nodes_l1

    // ---- stream s1: edge chain ----
    spmm_h<<<(edges + 7) / 8, 256, 0, s1>>>(ptr2, eAll, h2, hC, edges, 1);          // edges_l1
    spmm_h<<<(nodes + 7) / 8, 256, 0, s1>>>(ptr2 + NEDGES, eAll, hC, r, nodes, 0);  // inc@edges_l1
    gemm_tc<<<(nodes + 127) / 128, 256, SMEM, s1>>>(r, hW3, pf, nodes);             // @W2_10
    cudaEventRecord(evPart, s1);

    // ---- join + fused tail GEMM: sigmoid(q @ W2_00 + pf) ----
    cudaStreamWaitEvent(0, evPart, 0);
    gemm_final<<<(nodes + 127) / 128, 256, SMEM>>>(q, hW2, pf, (float*)d_out, nodes);
}

// round 16
// speedup vs baseline: 1.0493x; 1.0493x over previous
#include <cuda_runtime.h>
#include <cuda_fp16.h>
#include <mma.h>
#include <cstdint>

#define CDIM    128
#define NNODES  100000
#define NEDGES  200000
#define ADJ_MAX 3200000
#define INC_MAX 400000
#define NTOT    (NNODES + NEDGES + NNODES)
#define NINC    (NEDGES + NNODES)                 // 300000 inc-side rows
#define E_MAX   (ADJ_MAX + 2 * INC_MAX)
#define LDH     136

using namespace nvcuda;

// ---------------- scratch ----------------
__device__ __align__(128) __half g_hx [(size_t)NNODES * CDIM];   // x fp16
__device__ __align__(128) __half g_h1 [(size_t)NNODES * CDIM];   // x@W1_00
__device__ __align__(128) __half g_h2 [(size_t)NNODES * CDIM];   // x@W1_01
__device__ __align__(128) __half g_hB [(size_t)NNODES * CDIM];   // nodes_l1 = sig(adj@h1)
__device__ __align__(128) __half g_hC [(size_t)NEDGES * CDIM];   // edges_l1 = sig(incT@h2)
__device__ __align__(128) __half g_q  [(size_t)NNODES * CDIM];   // adj @ nodes_l1
__device__ __align__(128) __half g_r  [(size_t)NNODES * CDIM];   // inc @ edges_l1
__device__ __align__(128) __half g_pf [(size_t)NNODES * CDIM];   // (inc@edges_l1)@W2_10
__device__ __align__(128) __half g_hW [4][CDIM * CDIM];

__device__ int  g_cnt [NTOT];          // zero-initialized; scan_chunk restores zeros
__device__ int  g_work[NTOT];
__device__ int  g_ptr [NNODES + 1];    // adj CSR
__device__ int  g_ptr2[NINC + 1];      // incT rows then inc rows
__device__ int2 g_e   [E_MAX];
__device__ int  g_sums[256];           // [0:128) adj, [128:256) inc

__device__ __forceinline__ float sigf(float x) { return 1.f / (1.f + __expf(-x)); }
__device__ __forceinline__ unsigned h2u(__half2 h) { return *reinterpret_cast<unsigned*>(&h); }

// ---------------- converts: x + all 4 weights in ONE kernel ----------------
__global__ __launch_bounds__(256) void f2h_all(const float4* __restrict__ x, int xN4,
                                               const float4* __restrict__ w0,
                                               const float4* __restrict__ w1,
                                               const float4* __restrict__ w2,
                                               const float4* __restrict__ w3,
                                               uint2* __restrict__ outx,
                                               uint2* __restrict__ outw)
{
    int i = blockIdx.x * blockDim.x + threadIdx.x;
    if (i < xN4) {
        float4 v = x[i];
        outx[i] = make_uint2(h2u(__floats2half2_rn(v.x, v.y)),
                             h2u(__floats2half2_rn(v.z, v.w)));
    } else {
        int j = i - xN4;
        if (j < 16384) {
            const float4* src = (j < 4096) ? w0 : (j < 8192) ? w1 : (j < 12288) ? w2 : w3;
            float4 v = src[j & 4095];
            outw[j] = make_uint2(h2u(__floats2half2_rn(v.x, v.y)),
                                 h2u(__floats2half2_rn(v.z, v.w)));
        }
    }
}

// ---------------- tensor-core GEMM: outH = half(A @ W) ----------------
__global__ __launch_bounds__(256, 2) void gemm_tc(const __half* __restrict__ A,
                                                  const __half* __restrict__ W,
                                                  __half* __restrict__ out, int M)
{
    extern __shared__ char smem[];
    __half* sA = reinterpret_cast<__half*>(smem);
    __half* sW = reinterpret_cast<__half*>(smem + 128 * LDH * 2);
    float*  sO = reinterpret_cast<float*>(smem);

    const int tid  = threadIdx.x;
    const int row0 = blockIdx.x * 128;

    #pragma unroll
    for (int i = 0; i < 8; ++i) {
        int e = tid + i * 256;
        int r = e >> 4, c = e & 15;
        uint4 v = reinterpret_cast<const uint4*>(W)[e];
        *reinterpret_cast<uint4*>(&sW[r * LDH + c * 8]) = v;
    }
    #pragma unroll
    for (int i = 0; i < 8; ++i) {
        int e = tid + i * 256;
        int r = e >> 4, c = e & 15;
        uint4 v = make_uint4(0u, 0u, 0u, 0u);
        if (row0 + r < M) v = reinterpret_cast<const uint4*>(A)[(size_t)(row0 + r) * 16 + c];
        *reinterpret_cast<uint4*>(&sA[r * LDH + c * 8]) = v;
    }
    __syncthreads();

    const int warpId = tid >> 5;
    const int wr = warpId >> 1;
    const int wc = warpId & 1;

    wmma::fragment<wmma::accumulator, 16, 16, 16, float> c[2][4];
    #pragma unroll
    for (int i = 0; i < 2; ++i)
        #pragma unroll
        for (int j = 0; j < 4; ++j) wmma::fill_fragment(c[i][j], 0.f);

    #pragma unroll
    for (int k = 0; k < 8; ++k) {
        wmma::fragment<wmma::matrix_a, 16, 16, 16, __half, wmma::row_major> a[2];
        wmma::fragment<wmma::matrix_b, 16, 16, 16, __half, wmma::row_major> b[4];
        #pragma unroll
        for (int i = 0; i < 2; ++i)
            wmma::load_matrix_sync(a[i], &sA[(wr * 32 + i * 16) * LDH + k * 16], LDH);
        #pragma unroll
        for (int j = 0; j < 4; ++j)
            wmma::load_matrix_sync(b[j], &sW[(k * 16) * LDH + wc * 64 + j * 16], LDH);
        #pragma unroll
        for (int i = 0; i < 2; ++i)
            #pragma unroll
            for (int j = 0; j < 4; ++j)
                wmma::mma_sync(c[i][j], a[i], b[j], c[i][j]);
    }

    __syncthreads();
    #pragma unroll
    for (int i = 0; i < 2; ++i)
        #pragma unroll
        for (int j = 0; j < 4; ++j)
            wmma::store_matrix_sync(&sO[(wr * 32 + i * 16) * 128 + wc * 64 + j * 16],
                                    c[i][j], 128, wmma::mem_row_major);
    __syncthreads();

    #pragma unroll
    for (int i = 0; i < 16; ++i) {
        int e  = tid + i * 256;
        int r  = e >> 5, c4 = e & 31;
        int grow = row0 + r;
        if (grow < M) {
            float4 v = reinterpret_cast<float4*>(sO)[(size_t)r * 32 + c4];
            uint2 o = make_uint2(h2u(__floats2half2_rn(v.x, v.y)),
                                 h2u(__floats2half2_rn(v.z, v.w)));
            reinterpret_cast<uint2*>(out)[(size_t)grow * 32 + c4] = o;
        }
    }
}

// ---------------- fused final GEMM: out = sigmoid(A @ W + pf), fp32 out ----------
__global__ __launch_bounds__(256, 2) void gemm_final(const __half* __restrict__ A,
                                                     const __half* __restrict__ W,
                                                     const __half* __restrict__ pf,
                                                     float* __restrict__ out, int M)
{
    extern __shared__ char smem[];
    __half* sA = reinterpret_cast<__half*>(smem);
    __half* sW = reinterpret_cast<__half*>(smem + 128 * LDH * 2);
    float*  sO = reinterpret_cast<float*>(smem);

    const int tid  = threadIdx.x;
    const int row0 = blockIdx.x * 128;

    #pragma unroll
    for (int i = 0; i < 8; ++i) {
        int e = tid + i * 256;
        int r = e >> 4, c = e & 15;
        uint4 v = reinterpret_cast<const uint4*>(W)[e];
        *reinterpret_cast<uint4*>(&sW[r * LDH + c * 8]) = v;
    }
    #pragma unroll
    for (int i = 0; i < 8; ++i) {
        int e = tid + i * 256;
        int r = e >> 4, c = e & 15;
        uint4 v = make_uint4(0u, 0u, 0u, 0u);
        if (row0 + r < M) v = reinterpret_cast<const uint4*>(A)[(size_t)(row0 + r) * 16 + c];
        *reinterpret_cast<uint4*>(&sA[r * LDH + c * 8]) = v;
    }
    __syncthreads();

    const int warpId = tid >> 5;
    const int wr = warpId >> 1;
    const int wc = warpId & 1;

    wmma::fragment<wmma::accumulator, 16, 16, 16, float> c[2][4];
    #pragma unroll
    for (int i = 0; i < 2; ++i)
        #pragma unroll
        for (int j = 0; j < 4; ++j) wmma::fill_fragment(c[i][j], 0.f);

    #pragma unroll
    for (int k = 0; k < 8; ++k) {
        wmma::fragment<wmma::matrix_a, 16, 16, 16, __half, wmma::row_major> a[2];
        wmma::fragment<wmma::matrix_b, 16, 16, 16, __half, wmma::row_major> b[4];
        #pragma unroll
        for (int i = 0; i < 2; ++i)
            wmma::load_matrix_sync(a[i], &sA[(wr * 32 + i * 16) * LDH + k * 16], LDH);
        #pragma unroll
        for (int j = 0; j < 4; ++j)
            wmma::load_matrix_sync(b[j], &sW[(k * 16) * LDH + wc * 64 + j * 16], LDH);
        #pragma unroll
        for (int i = 0; i < 2; ++i)
            #pragma unroll
            for (int j = 0; j < 4; ++j)
                wmma::mma_sync(c[i][j], a[i], b[j], c[i][j]);
    }

    __syncthreads();
    #pragma unroll
    for (int i = 0; i < 2; ++i)
        #pragma unroll
        for (int j = 0; j < 4; ++j)
            wmma::store_matrix_sync(&sO[(wr * 32 + i * 16) * 128 + wc * 64 + j * 16],
                                    c[i][j], 128, wmma::mem_row_major);
    __syncthreads();

    #pragma unroll
    for (int i = 0; i < 16; ++i) {
        int e  = tid + i * 256;
        int r  = e >> 5, c4 = e & 31;
        int grow = row0 + r;
        if (grow < M) {
            float4 v = reinterpret_cast<float4*>(sO)[(size_t)r * 32 + c4];
            uint2 pu = reinterpret_cast<const uint2*>(pf)[(size_t)grow * 32 + c4];
            float2 p0 = __half22float2(*reinterpret_cast<__half2*>(&pu.x));
            float2 p1 = __half22float2(*reinterpret_cast<__half2*>(&pu.y));
            float4 o = make_float4(sigf(v.x + p0.x), sigf(v.y + p0.y),
                                   sigf(v.z + p1.x), sigf(v.w + p1.y));
            reinterpret_cast<float4*>(out)[(size_t)grow * 32 + c4] = o;
        }
    }
}

// ---------------- CSR builds ----------------
__global__ __launch_bounds__(256) void hist_adj(const int* __restrict__ rows, int nnz,
                                                int* __restrict__ cnt)
{
    int i = blockIdx.x * blockDim.x + threadIdx.x;
    if (i < nnz) atomicAdd(&cnt[rows[i]], 1);
}

__global__ __launch_bounds__(256) void hist_inc(const int* __restrict__ inc_rows,
                                                const int* __restrict__ inc_cols, int nnz,
                                                int* __restrict__ cnt)
{
    int i = blockIdx.x * blockDim.x + threadIdx.x;
    if (i < nnz) {
        atomicAdd(&cnt[inc_cols[i]], 1);            // incT rows (edge ids)
        atomicAdd(&cnt[NEDGES + inc_rows[i]], 1);   // inc rows (node ids)
    }
}

// scan + self-restoring scratch: zeroes `in` (cnt) after reading, so the next
// graph replay starts from a clean histogram without a memset launch.
__global__ __launch_bounds__(1024) void scan_chunk(int* __restrict__ in,
                                                   int* __restrict__ out,
                                                   int* __restrict__ sums, int n)
{
    __shared__ int sh[1024];
    int t = threadIdx.x;
    int idx = blockIdx.x * 4096 + t * 4;
    int a0 = (idx     < n) ? in[idx]     : 0;
    int a1 = (idx + 1 < n) ? in[idx + 1] : 0;
    int a2 = (idx + 2 < n) ? in[idx + 2] : 0;
    int a3 = (idx + 3 < n) ? in[idx + 3] : 0;
    if (idx     < n) in[idx]     = 0;
    if (idx + 1 < n) in[idx + 1] = 0;
    if (idx + 2 < n) in[idx + 2] = 0;
    if (idx + 3 < n) in[idx + 3] = 0;
    int s = a0 + a1 + a2 + a3;
    sh[t] = s;
    __syncthreads();
    for (int off = 1; off < 1024; off <<= 1) {
        int v = (t >= off) ? sh[t - off] : 0;
        __syncthreads();
        sh[t] += v;
        __syncthreads();
    }
    int excl = sh[t] - s;
    if (idx     < n) out[idx]     = excl;
    if (idx + 1 < n) out[idx + 1] = excl + a0;
    if (idx + 2 < n) out[idx + 2] = excl + a0 + a1;
    if (idx + 3 < n) out[idx + 3] = excl + a0 + a1 + a2;
    if (t == 1023) sums[blockIdx.x] = sh[1023];
}

__global__ __launch_bounds__(256) void add_base_scan(int* __restrict__ ptr,
                                                     int* __restrict__ work,
                                                     const int* __restrict__ sums,
                                                     int n, int base, int end)
{
    __shared__ int sh[128];
    int t = threadIdx.x;
    if (t < 128) sh[t] = sums[t];
    __syncthreads();
    for (int off = 1; off < 128; off <<= 1) {
        int v = (t < 128 && t >= off) ? sh[t - off] : 0;
        __syncthreads();
        if (t < 128) sh[t] += v;
        __syncthreads();
    }
    int i = blockIdx.x * blockDim.x + t;
    if (i < n) {
        int blk = i >> 12;
        int pre = (blk == 0) ? 0 : sh[blk - 1];
        int v = ptr[i] + pre + base;
        ptr[i]  = v;
        work[i] = v;
    }
    if (i == 0) ptr[n] = end;
}

__global__ __launch_bounds__(256) void scatter_adj(const int* __restrict__ rows,
                                                   const int* __restrict__ cols,
                                                   const float* __restrict__ vals, int nnz,
                                                   int* __restrict__ work,
                                                   int2* __restrict__ e)
{
    int i = blockIdx.x * blockDim.x + threadIdx.x;
    if (i >= nnz) return;
    int p = atomicAdd(&work[rows[i]], 1);
    e[p] = make_int2(cols[i], __float_as_int(vals[i]));
}

__global__ __launch_bounds__(256) void scatter_inc(const int* __restrict__ inc_rows,
                                                   const int* __restrict__ inc_cols,
                                                   const float* __restrict__ inc_vals, int nnz,
                                                   int* __restrict__ work,
                                                   int2* __restrict__ e)
{
    int i = blockIdx.x * blockDim.x + threadIdx.x;
    if (i >= nnz) return;
    int vv = __float_as_int(inc_vals[i]);
    int p = atomicAdd(&work[inc_cols[i]], 1);
    e[p] = make_int2(inc_rows[i], vv);
    int q = atomicAdd(&work[NEDGES + inc_rows[i]], 1);
    e[q] = make_int2(inc_cols[i], vv);
}

// ---------------- CSR SpMM: warp per row, fp16 in, fp16 out (optional sigmoid) -----
__device__ __forceinline__ void gather_fma(float4& acc, int2 t,
                                           const uint2* __restrict__ Xu, int lane)
{
    float v  = __int_as_float(t.y);
    uint2 u  = __ldg(&Xu[(size_t)t.x * 32 + lane]);
    float2 f0 = __half22float2(*reinterpret_cast<__half2*>(&u.x));
    float2 f1 = __half22float2(*reinterpret_cast<__half2*>(&u.y));
    acc.x += v * f0.x; acc.y += v * f0.y; acc.z += v * f1.x; acc.w += v * f1.y;
}

__global__ __launch_bounds__(256) void spmm_h(const int* __restrict__ ptr,
                                              const int2* __restrict__ e,
                                              const __half* __restrict__ X,
                                              __half* __restrict__ out,
                                              int nrows, int applySig)
{
    __shared__ int2 se[8][32];
    int w    = (blockIdx.x * blockDim.x + threadIdx.x) >> 5;
    int lane = threadIdx.x & 31;
    int wl   = threadIdx.x >> 5;
    if (w >= nrows) return;
    const uint2* Xu = reinterpret_cast<const uint2*>(X);
    int start = ptr[w], end = ptr[w + 1];
    float4 acc = make_float4(0.f, 0.f, 0.f, 0.f);
    for (int i = start; i < end; i += 32) {
        int take = min(32, end - i);
        if (lane < take) se[wl][lane] = e[i + lane];
        __syncwarp();
        if (take == 32) {
            #pragma unroll 8
            for (int j = 0; j < 32; ++j) gather_fma(acc, se[wl][j], Xu, lane);
        } else {
            for (int j = 0; j < take; ++j) gather_fma(acc, se[wl][j], Xu, lane);
        }
        __syncwarp();
    }
    if (applySig) {
        acc.x = sigf(acc.x); acc.y = sigf(acc.y); acc.z = sigf(acc.z); acc.w = sigf(acc.w);
    }
    uint2 o = make_uint2(h2u(__floats2half2_rn(acc.x, acc.y)),
                         h2u(__floats2half2_rn(acc.z, acc.w)));
    reinterpret_cast<uint2*>(out)[(size_t)w * 32 + lane] = o;
}

// ---------------- host ----------------
extern "C" void kernel_launch(void* const* d_in, const int* in_sizes, int n_in,
                              void* d_out, int out_size)
{
    const float* x        = (const float*)d_in[0];
    const float* W1_00    = (const float*)d_in[1];
    const float* W1_01    = (const float*)d_in[2];
    const float* W2_00    = (const float*)d_in[3];
    const float* W2_10    = (const float*)d_in[4];
    const int*   adj_rows = (const int*)  d_in[5];
    const int*   adj_cols = (const int*)  d_in[6];
    const float* adj_vals = (const float*)d_in[7];
    const int*   inc_rows = (const int*)  d_in[8];
    const int*   inc_cols = (const int*)  d_in[9];
    const float* inc_vals = (const float*)d_in[10];
    const int adj_nnz = in_sizes[5];
    const int inc_nnz = in_sizes[8];
    const int nodes   = NNODES;
    const int edges   = NEDGES;

    __half *hx, *h1, *h2, *hB, *hC, *q, *r, *pf, *hW;
    int *cnt, *ptr, *ptr2, *work, *sums;
    int2 *eAll;
    cudaGetSymbolAddress((void**)&hx, g_hx);
    cudaGetSymbolAddress((void**)&h1, g_h1);
    cudaGetSymbolAddress((void**)&h2, g_h2);
    cudaGetSymbolAddress((void**)&hB, g_hB);
    cudaGetSymbolAddress((void**)&hC, g_hC);
    cudaGetSymbolAddress((void**)&q,  g_q);
    cudaGetSymbolAddress((void**)&r,  g_r);
    cudaGetSymbolAddress((void**)&pf, g_pf);
    cudaGetSymbolAddress((void**)&hW, g_hW);
    cudaGetSymbolAddress((void**)&cnt,  g_cnt);
    cudaGetSymbolAddress((void**)&ptr,  g_ptr);
    cudaGetSymbolAddress((void**)&ptr2, g_ptr2);
    cudaGetSymbolAddress((void**)&work, g_work);
    cudaGetSymbolAddress((void**)&sums, g_sums);
    cudaGetSymbolAddress((void**)&eAll, g_e);

    __half* hW0 = hW;
    __half* hW1 = hW + CDIM * CDIM;
    __half* hW2 = hW + 2 * CDIM * CDIM;
    __half* hW3 = hW + 3 * CDIM * CDIM;

    static cudaStream_t s1 = nullptr;
    static cudaEvent_t evFork = nullptr, evG1 = nullptr, evPart = nullptr;
    if (!s1) {
        cudaStreamCreateWithFlags(&s1, cudaStreamNonBlocking);
        cudaEventCreateWithFlags(&evFork, cudaEventDisableTiming);
        cudaEventCreateWithFlags(&evG1,   cudaEventDisableTiming);
        cudaEventCreateWithFlags(&evPart, cudaEventDisableTiming);
        cudaFuncSetAttribute(gemm_tc, cudaFuncAttributeMaxDynamicSharedMemorySize,
                             128 * LDH * 2 * 2);
        cudaFuncSetAttribute(gemm_final, cudaFuncAttributeMaxDynamicSharedMemorySize,
                             128 * LDH * 2 * 2);
    }
    const int SMEM = 128 * LDH * 2 * 2;

    // ---- fork ----
    cudaEventRecord(evFork, 0);
    cudaStreamWaitEvent(s1, evFork, 0);

    // ---- stream 0: adj CSR build (cnt self-restored by scan_chunk; no memset) ----
    hist_adj<<<(adj_nnz + 255) / 256, 256>>>(adj_rows, adj_nnz, cnt);
    {
        int nB = (NNODES + 4095) / 4096;
        scan_chunk<<<nB, 1024>>>(cnt, ptr, sums, NNODES);
        add_base_scan<<<(NNODES + 255) / 256, 256>>>(ptr, work, sums, NNODES, 0, adj_nnz);
    }
    scatter_adj<<<(adj_nnz + 255) / 256, 256>>>(adj_rows, adj_cols, adj_vals, adj_nnz,
                                                work, eAll);

    // ---- stream s1: converts + level-1 GEMMs ----
    int xN4 = nodes * CDIM / 4;
    f2h_all<<<(xN4 + 16384 + 255) / 256, 256, 0, s1>>>((const float4*)x, xN4,
                                                       (const float4*)W1_00, (const float4*)W1_01,
                                                       (const float4*)W2_00, (const float4*)W2_10,
                                                       (uint2*)hx, (uint2*)hW0);
    gemm_tc<<<(nodes + 127) / 128, 256, SMEM, s1>>>(hx, hW0, h1, nodes);
    cudaEventRecord(evG1, s1);
    gemm_tc<<<(nodes + 127) / 128, 256, SMEM, s1>>>(hx, hW1, h2, nodes);

    // ---- stream s1: inc CSR build (no memset) ----
    hist_inc<<<(inc_nnz + 255) / 256, 256, 0, s1>>>(inc_rows, inc_cols, inc_nnz, cnt + NNODES);
    {
        int nB = (NINC + 4095) / 4096;
        scan_chunk<<<nB, 1024, 0, s1>>>(cnt + NNODES, ptr2, sums + 128, NINC);
        add_base_scan<<<(NINC + 255) / 256, 256, 0, s1>>>(ptr2, work + NNODES, sums + 128,
                                                          NINC, adj_nnz,
                                                          adj_nnz + 2 * inc_nnz);
    }
    scatter_inc<<<(inc_nnz + 255) / 256, 256, 0, s1>>>(inc_rows, inc_cols, inc_vals, inc_nnz,
                                                       work + NNODES, eAll);

    // ---- stream 0: node chain (S1 -> q) ----
    cudaStreamWaitEvent(0, evG1, 0);
    spmm_h<<<(nodes + 7) / 8, 256>>>(ptr, eAll, h1, hB, nodes, 1);      // nodes_l1
    spmm_h<<<(nodes + 7) / 8, 256>>>(ptr, eAll, hB, q, nodes, 0);       // adj @ nodes_l1

    // ---- stream s1: edge chain ----
    spmm_h<<<(edges + 7) / 8, 256, 0, s1>>>(ptr2, eAll, h2, hC, edges, 1);          // edges_l1
    spmm_h<<<(nodes + 7) / 8, 256, 0, s1>>>(ptr2 + NEDGES, eAll, hC, r, nodes, 0);  // inc@edges_l1
    gemm_tc<<<(nodes + 127) / 128, 256, SMEM, s1>>>(r, hW3, pf, nodes);             // @W2_10
    cudaEventRecord(evPart, s1);

    // ---- join + fused tail GEMM: sigmoid(q @ W2_00 + pf) ----
    cudaStreamWaitEvent(0, evPart, 0);
    gemm_final<<<(nodes + 127) / 128, 256, SMEM>>>(q, hW2, pf, (float*)d_out, nodes);
}